// round 7
// baseline (speedup 1.0000x reference)
#include <cuda_runtime.h>
#include <cstdint>

// ============================================================================
// out[16384,4096] = x @ ((W_int - zp)*scale)^T + bias
// Build target is plain sm_103 (no tcgen05). Use tf32 mma.sync (HMMA):
//   - W_int values are integers in [-128,127): EXACT in tf32 (raw f32 bits).
//   - x converted with cvt.rna.tf32.f32 (rel err ~2^-12 -> result ~1e-4).
//   - fp32 epilogue: out = scale*G - (scale*zp)*rowsum(x) + bias.
// ============================================================================

#define M_TOTAL 16384
#define N_TOTAL 4096
#define K_TOTAL 4096
#define BM 128
#define BN 128
#define BK 32
#define NSTAGES 4
#define NITERS (K_TOTAL / BK)      // 128
#define STRIDE 36                  // smem word stride; 36 % 32 == 4 -> conflict-free frags
#define TILE_WORDS (128 * STRIDE)  // 4608 words = 18 KB per operand per stage
#define SMEM_BYTES (NSTAGES * 2 * TILE_WORDS * 4)   // 147456 B

__device__ float g_rs[M_TOTAL];    // per-row sum of x (zero_point term)

#define CP16(sa, g) \
    asm volatile("cp.async.cg.shared.global [%0], [%1], 16;" :: "r"(sa), "l"(g))
#define CP_COMMIT() asm volatile("cp.async.commit_group;" ::: "memory")
#define CP_WAIT(n)  asm volatile("cp.async.wait_group %0;" :: "n"(n) : "memory")

__device__ __forceinline__ uint32_t f2tf32(float f) {
    uint32_t u;
    asm("cvt.rna.tf32.f32 %0, %1;" : "=r"(u) : "f"(f));
    return u;
}

#define MMA_TF32(d, a, b)                                                      \
    asm volatile("mma.sync.aligned.m16n8k8.row.col.f32.tf32.tf32.f32 "         \
                 "{%0,%1,%2,%3},{%4,%5,%6,%7},{%8,%9},{%0,%1,%2,%3};"          \
                 : "+f"((d)[0]), "+f"((d)[1]), "+f"((d)[2]), "+f"((d)[3])      \
                 : "r"((a)[0]), "r"((a)[1]), "r"((a)[2]), "r"((a)[3]),         \
                   "r"((b)[0]), "r"((b)[1]))

// ============================================================================
// Kernel 1: per-row sum of x (for zero_point term). One warp per row.
// ============================================================================
__global__ void __launch_bounds__(256) rowsum_kernel(const float* __restrict__ x) {
    int row = blockIdx.x * 8 + (threadIdx.x >> 5);
    int lane = threadIdx.x & 31;
    const float4* xr = reinterpret_cast<const float4*>(x + (size_t)row * K_TOTAL);
    float s = 0.f;
#pragma unroll 8
    for (int i = lane; i < K_TOTAL / 4; i += 32) {
        float4 v = xr[i];
        s += (v.x + v.y) + (v.z + v.w);
    }
#pragma unroll
    for (int o = 16; o > 0; o >>= 1) s += __shfl_xor_sync(0xffffffffu, s, o);
    if (lane == 0) g_rs[row] = s;
}

// ============================================================================
// Kernel 2: tf32 tensor-core GEMM, 128x128 tile, 4-stage cp.async pipeline
// ============================================================================
__device__ __forceinline__ void load_tile(const float* __restrict__ gA,
                                          const float* __restrict__ gB,
                                          uint32_t sA, uint32_t sB,
                                          int kk, int stage) {
    // each thread: 4x16B for A, 4x16B for B. row = tid>>1, half = (tid&1)*16 floats
    uint32_t so = (uint32_t)stage * (TILE_WORDS * 4);
#pragma unroll
    for (int i = 0; i < 4; i++) {
        CP16(sA + so + i * 16u, gA + kk + i * 4);
        CP16(sB + so + i * 16u, gB + kk + i * 4);
    }
}

__global__ void __launch_bounds__(256, 1) gemm_kernel(
    const float* __restrict__ x, const float* __restrict__ w,
    const float* __restrict__ scales, const float* __restrict__ zp,
    const float* __restrict__ bias, float* __restrict__ out) {
    extern __shared__ float smem[];
    const int tid = threadIdx.x;
    const int lane = tid & 31;
    const int wid = tid >> 5;
    const int warp_m = wid >> 2;          // 0..1  (64 rows each)
    const int warp_n = wid & 3;           // 0..3  (32 cols each)
    const int m0 = blockIdx.y * BM;
    const int n0 = blockIdx.x * BN;

    float* As = smem;                               // [stage][128][STRIDE]
    float* Bs = smem + NSTAGES * TILE_WORDS;

    // ---- cp.async source/dest for this thread ----
    const int ld_row = tid >> 1;                    // 0..127
    const int ld_half = (tid & 1) * 16;             // float offset within row
    const float* gA = x + (size_t)(m0 + ld_row) * K_TOTAL + ld_half;
    const float* gB = w + (size_t)(n0 + ld_row) * K_TOTAL + ld_half;
    uint32_t sA = (uint32_t)__cvta_generic_to_shared(As + ld_row * STRIDE + ld_half);
    uint32_t sB = (uint32_t)__cvta_generic_to_shared(Bs + ld_row * STRIDE + ld_half);

    // ---- accumulators ----
    float acc[4][4][4];
#pragma unroll
    for (int i = 0; i < 4; i++)
#pragma unroll
        for (int j = 0; j < 4; j++)
#pragma unroll
            for (int k = 0; k < 4; k++) acc[i][j][k] = 0.f;

    const int g = lane >> 2;              // groupID
    const int t = lane & 3;               // threadID_in_group

    // prologue: fill NSTAGES-1 stages
#pragma unroll
    for (int p = 0; p < NSTAGES - 1; p++) {
        load_tile(gA, gB, sA, sB, p * BK, p);
        CP_COMMIT();
    }

    for (int it = 0; it < NITERS; it++) {
        CP_WAIT(NSTAGES - 2);
        __syncthreads();

        int nxt = it + NSTAGES - 1;
        if (nxt < NITERS) load_tile(gA, gB, sA, sB, nxt * BK, nxt & (NSTAGES - 1));
        CP_COMMIT();

        const float* A = As + (it & (NSTAGES - 1)) * TILE_WORDS;
        const float* B = Bs + (it & (NSTAGES - 1)) * TILE_WORDS;
#pragma unroll
        for (int ks = 0; ks < 4; ks++) {
            const int kb = ks * 8;
            uint32_t af[4][4];
#pragma unroll
            for (int mt = 0; mt < 4; mt++) {
                const float* ap = A + (warp_m * 64 + mt * 16 + g) * STRIDE + kb + t;
                af[mt][0] = f2tf32(ap[0]);
                af[mt][1] = f2tf32(ap[8 * STRIDE]);
                af[mt][2] = f2tf32(ap[4]);
                af[mt][3] = f2tf32(ap[8 * STRIDE + 4]);
            }
            uint32_t bf[4][2];
#pragma unroll
            for (int nt = 0; nt < 4; nt++) {
                const float* bp = B + (warp_n * 32 + nt * 8 + g) * STRIDE + kb + t;
                bf[nt][0] = __float_as_uint(bp[0]);   // int-valued: exact as tf32
                bf[nt][1] = __float_as_uint(bp[4]);
            }
#pragma unroll
            for (int mt = 0; mt < 4; mt++)
#pragma unroll
                for (int nt = 0; nt < 4; nt++) MMA_TF32(acc[mt][nt], af[mt], bf[nt]);
        }
    }

    // ---- epilogue: out = acc*scale - (scale*zp)*rowsum + bias ----
    float sc[8], szp[8], bi[8];
#pragma unroll
    for (int nt = 0; nt < 4; nt++) {
#pragma unroll
        for (int q = 0; q < 2; q++) {
            int n = n0 + warp_n * 32 + nt * 8 + t * 2 + q;
            float s = __ldg(scales + n);
            sc[nt * 2 + q] = s;
            szp[nt * 2 + q] = s * __ldg(zp + n);
            bi[nt * 2 + q] = __ldg(bias + n);
        }
    }
    float rs[8];
#pragma unroll
    for (int mt = 0; mt < 4; mt++) {
        rs[mt * 2 + 0] = g_rs[m0 + warp_m * 64 + mt * 16 + g];
        rs[mt * 2 + 1] = g_rs[m0 + warp_m * 64 + mt * 16 + g + 8];
    }
#pragma unroll
    for (int mt = 0; mt < 4; mt++) {
#pragma unroll
        for (int h = 0; h < 2; h++) {
            int row = m0 + warp_m * 64 + mt * 16 + g + h * 8;
            float r = rs[mt * 2 + h];
#pragma unroll
            for (int nt = 0; nt < 4; nt++) {
                int col = n0 + warp_n * 32 + nt * 8 + t * 2;
                float2 v;
                v.x = acc[mt][nt][h * 2 + 0] * sc[nt * 2 + 0] - szp[nt * 2 + 0] * r + bi[nt * 2 + 0];
                v.y = acc[mt][nt][h * 2 + 1] * sc[nt * 2 + 1] - szp[nt * 2 + 1] * r + bi[nt * 2 + 1];
                *reinterpret_cast<float2*>(out + (size_t)row * N_TOTAL + col) = v;
            }
        }
    }
}

// ============================================================================
// Launch
// ============================================================================
extern "C" void kernel_launch(void* const* d_in, const int* in_sizes, int n_in,
                              void* d_out, int out_size) {
    const float* x      = (const float*)d_in[0];
    const float* wf     = (const float*)d_in[1];
    const float* scales = (const float*)d_in[2];
    const float* zp     = (const float*)d_in[3];
    const float* bias   = (const float*)d_in[4];
    float* out = (float*)d_out;

    rowsum_kernel<<<M_TOTAL / 8, 256>>>(x);

    cudaFuncSetAttribute(gemm_kernel, cudaFuncAttributeMaxDynamicSharedMemorySize,
                         SMEM_BYTES);
    dim3 grid(N_TOTAL / BN, M_TOTAL / BM, 1);   // n-fastest: A block reused across wave
    gemm_kernel<<<grid, 256, SMEM_BYTES>>>(x, wf, scales, zp, bias, out);
}

// round 9
// speedup vs baseline: 1.6130x; 1.6130x over previous
#include <cuda_runtime.h>
#include <cstdint>

// ============================================================================
// out[16384,4096] = x @ ((W_int - zp)*scale)^T + bias       (sm_103, no tcgen05)
// tf32 mma.sync (HMMA). W ints exact in tf32 (raw bits). x pre-rounded (rna)
// in a prepass. ldmatrix fragment loads, XOR-swizzled SMEM, 3-stage cp.async,
// 2 CTAs/SM. Epilogue: out = scale*G - (scale*zp)*rowsum(x) + bias.
// (Resubmission of R7 kernel — R8 bench was an infra failure, kernel never ran.)
// ============================================================================

#define M_TOTAL 16384
#define N_TOTAL 4096
#define K_TOTAL 4096
#define BM 128
#define BN 128
#define BK 32
#define NST 3
#define NITERS (K_TOTAL / BK)          // 128
#define ASTAGE 16384                   // bytes per operand per stage (128 x 128B)
#define SMEM_BYTES (NST * 2 * ASTAGE)  // 98304

__device__ float g_xa[(size_t)M_TOTAL * K_TOTAL];   // tf32-rounded x
__device__ float g_rs[M_TOTAL];                     // per-row sum of x

#define CP16(sa, g) \
    asm volatile("cp.async.cg.shared.global [%0], [%1], 16;" :: "r"(sa), "l"(g))
#define CP_COMMIT() asm volatile("cp.async.commit_group;" ::: "memory")
#define CP_WAIT(n)  asm volatile("cp.async.wait_group %0;" :: "n"(n) : "memory")

__device__ __forceinline__ uint32_t f2tf32(float f) {
    uint32_t u;
    asm("cvt.rna.tf32.f32 %0, %1;" : "=r"(u) : "f"(f));
    return u;
}

#define LDSM4(r, addr) \
    asm volatile("ldmatrix.sync.aligned.m8n8.x4.shared.b16 {%0,%1,%2,%3}, [%4];" \
                 : "=r"((r)[0]), "=r"((r)[1]), "=r"((r)[2]), "=r"((r)[3]) \
                 : "r"(addr))

#define MMA_TF32(d, a, b0, b1)                                                 \
    asm volatile("mma.sync.aligned.m16n8k8.row.col.f32.tf32.tf32.f32 "         \
                 "{%0,%1,%2,%3},{%4,%5,%6,%7},{%8,%9},{%0,%1,%2,%3};"          \
                 : "+f"((d)[0]), "+f"((d)[1]), "+f"((d)[2]), "+f"((d)[3])      \
                 : "r"((a)[0]), "r"((a)[1]), "r"((a)[2]), "r"((a)[3]),         \
                   "r"(b0), "r"(b1))

// ============================================================================
// Kernel 1: x -> tf32-rounded copy + per-row sum. One warp per row.
// ============================================================================
__global__ void __launch_bounds__(256) prep_kernel(const float* __restrict__ x) {
    int row = blockIdx.x * 8 + (threadIdx.x >> 5);
    int lane = threadIdx.x & 31;
    const float4* xr = reinterpret_cast<const float4*>(x + (size_t)row * K_TOTAL);
    float4* xo = reinterpret_cast<float4*>(g_xa + (size_t)row * K_TOTAL);
    float s = 0.f;
#pragma unroll 4
    for (int i = lane; i < K_TOTAL / 4; i += 32) {
        float4 v = xr[i];
        s += (v.x + v.y) + (v.z + v.w);
        float4 o;
        o.x = __uint_as_float(f2tf32(v.x));
        o.y = __uint_as_float(f2tf32(v.y));
        o.z = __uint_as_float(f2tf32(v.z));
        o.w = __uint_as_float(f2tf32(v.w));
        xo[i] = o;
    }
#pragma unroll
    for (int o = 16; o > 0; o >>= 1) s += __shfl_xor_sync(0xffffffffu, s, o);
    if (lane == 0) g_rs[row] = s;
}

// ============================================================================
// Kernel 2: tf32 GEMM. 128x128x32 tile, 3-stage pipeline, ldmatrix frags.
// SMEM row = 128B (8 chunks of 16B); chunk c of row r stored at c ^ (r & 7).
// ============================================================================
__device__ __forceinline__ void load_tile(const float* __restrict__ gA,
                                          const float* __restrict__ gB,
                                          uint32_t sAst, uint32_t sBst,
                                          const uint32_t* soff, int cb, int kk) {
#pragma unroll
    for (int i = 0; i < 4; i++) {
        CP16(sAst + soff[i], gA + kk + (cb + i) * 4);
        CP16(sBst + soff[i], gB + kk + (cb + i) * 4);
    }
}

__global__ void __launch_bounds__(256, 2) gemm_kernel(
    const float* __restrict__ w,
    const float* __restrict__ scales, const float* __restrict__ zp,
    const float* __restrict__ bias, float* __restrict__ out) {
    extern __shared__ float smem[];
    const uint32_t sbase = (uint32_t)__cvta_generic_to_shared(smem);
    const int tid = threadIdx.x;
    const int lane = tid & 31;
    const int wid = tid >> 5;
    const int warp_m = wid >> 2;            // 0..1 (64 rows)
    const int warp_n = wid & 3;             // 0..3 (32 cols)
    const int m0 = blockIdx.y * BM;
    const int n0 = blockIdx.x * BN;

    // ---- loader: row = tid>>1, chunks cb..cb+3 (16B each), swizzled ----
    const int lr = tid >> 1;
    const int cb = (tid & 1) * 4;
    const float* gA = g_xa + (size_t)(m0 + lr) * K_TOTAL;
    const float* gB = w + (size_t)(n0 + lr) * K_TOTAL;
    uint32_t soff[4];
#pragma unroll
    for (int i = 0; i < 4; i++)
        soff[i] = (uint32_t)(lr * 128 + (((cb + i) ^ (lr & 7)) << 4));

    // ---- ldmatrix per-lane addressing (row & 7 == lane & 7 for all frags) ----
    const uint32_t sa = lane & 7;
    const uint32_t c0a = lane >> 4;          // A: chunk parity
    const uint32_t c0b = (lane >> 3) & 1;    // B: chunk parity
    uint32_t aoff[4];
#pragma unroll
    for (int mt = 0; mt < 4; mt++) {
        int rowA = warp_m * 64 + mt * 16 + ((lane >> 3) & 1) * 8 + (lane & 7);
        aoff[mt] = (uint32_t)(rowA * 128);
    }
    uint32_t boff[2];
#pragma unroll
    for (int bg = 0; bg < 2; bg++) {
        int rowB = warp_n * 32 + bg * 16 + ((lane >> 4) & 1) * 8 + (lane & 7);
        boff[bg] = (uint32_t)(rowB * 128);
    }

    float acc[4][4][4];
#pragma unroll
    for (int i = 0; i < 4; i++)
#pragma unroll
        for (int j = 0; j < 4; j++)
#pragma unroll
            for (int k = 0; k < 4; k++) acc[i][j][k] = 0.f;

    // ---- prologue: fill 2 of 3 stages ----
    load_tile(gA, gB, sbase, sbase + NST * ASTAGE, soff, cb, 0);
    CP_COMMIT();
    load_tile(gA, gB, sbase + ASTAGE, sbase + NST * ASTAGE + ASTAGE, soff, cb, BK);
    CP_COMMIT();

    int sidx = 0;
    for (int it = 0; it < NITERS; it++) {
        CP_WAIT(1);
        __syncthreads();

        int nidx = sidx + 2; if (nidx >= NST) nidx -= NST;
        int nxt = it + 2;
        if (nxt < NITERS)
            load_tile(gA, gB, sbase + nidx * ASTAGE,
                      sbase + NST * ASTAGE + nidx * ASTAGE, soff, cb, nxt * BK);
        CP_COMMIT();

        const uint32_t Ab = sbase + sidx * ASTAGE;
        const uint32_t Bb = sbase + NST * ASTAGE + sidx * ASTAGE;
#pragma unroll
        for (int ks = 0; ks < 4; ks++) {
            uint32_t a[4][4];
#pragma unroll
            for (int mt = 0; mt < 4; mt++)
                LDSM4(a[mt], Ab + aoff[mt] + ((((uint32_t)(2 * ks) + c0a) ^ sa) << 4));
            uint32_t b[2][4];
#pragma unroll
            for (int bg = 0; bg < 2; bg++)
                LDSM4(b[bg], Bb + boff[bg] + ((((uint32_t)(2 * ks) + c0b) ^ sa) << 4));
#pragma unroll
            for (int mt = 0; mt < 4; mt++)
#pragma unroll
                for (int nt = 0; nt < 4; nt++)
                    MMA_TF32(acc[mt][nt], a[mt], b[nt >> 1][(nt & 1) * 2],
                             b[nt >> 1][(nt & 1) * 2 + 1]);
        }
        sidx++; if (sidx >= NST) sidx = 0;
    }

    // ---- epilogue: out = acc*scale - (scale*zp)*rowsum + bias ----
    const int g = lane >> 2;
    const int t = lane & 3;
    float sc[8], szp[8], bi[8];
#pragma unroll
    for (int nt = 0; nt < 4; nt++) {
#pragma unroll
        for (int q = 0; q < 2; q++) {
            int n = n0 + warp_n * 32 + nt * 8 + t * 2 + q;
            float s = __ldg(scales + n);
            sc[nt * 2 + q] = s;
            szp[nt * 2 + q] = s * __ldg(zp + n);
            bi[nt * 2 + q] = __ldg(bias + n);
        }
    }
#pragma unroll
    for (int mt = 0; mt < 4; mt++) {
#pragma unroll
        for (int h = 0; h < 2; h++) {
            int row = m0 + warp_m * 64 + mt * 16 + g + h * 8;
            float r = g_rs[row];
#pragma unroll
            for (int nt = 0; nt < 4; nt++) {
                int col = n0 + warp_n * 32 + nt * 8 + t * 2;
                float2 v;
                v.x = acc[mt][nt][h * 2 + 0] * sc[nt * 2 + 0] - szp[nt * 2 + 0] * r + bi[nt * 2 + 0];
                v.y = acc[mt][nt][h * 2 + 1] * sc[nt * 2 + 1] - szp[nt * 2 + 1] * r + bi[nt * 2 + 1];
                *reinterpret_cast<float2*>(out + (size_t)row * N_TOTAL + col) = v;
            }
        }
    }
}

// ============================================================================
// Launch
// ============================================================================
extern "C" void kernel_launch(void* const* d_in, const int* in_sizes, int n_in,
                              void* d_out, int out_size) {
    const float* x      = (const float*)d_in[0];
    const float* wf     = (const float*)d_in[1];
    const float* scales = (const float*)d_in[2];
    const float* zp     = (const float*)d_in[3];
    const float* bias   = (const float*)d_in[4];
    float* out = (float*)d_out;

    prep_kernel<<<M_TOTAL / 8, 256>>>(x);

    cudaFuncSetAttribute(gemm_kernel, cudaFuncAttributeMaxDynamicSharedMemorySize,
                         SMEM_BYTES);
    dim3 grid(N_TOTAL / BN, M_TOTAL / BM, 1);   // n-fastest: W tiles L2-resident
    gemm_kernel<<<grid, 256, SMEM_BYTES>>>(wf, scales, zp, bias, out);
}